// round 2
// baseline (speedup 1.0000x reference)
#include <cuda_runtime.h>
#include <cuda_bf16.h>

// Problem constants (match reference_code)
#define N_NODES 100000
#define N_EDGES 3200000
#define D_FEAT  16
#define N_LAYERS 12

#define SCAN_B 1024
#define NB ((N_NODES + SCAN_B - 1) / SCAN_B)

// ---- scratch (device globals; no allocation allowed) ----
__device__ float  g_h[2][N_NODES * D_FEAT];     // ping-pong feature buffers
__device__ float  g_inv_sqrt[N_NODES];
__device__ float  g_self[N_NODES];              // 1/deg
__device__ int    g_cnt[N_NODES];               // dst-degree counts
__device__ int    g_nonisol[N_NODES];
__device__ int    g_row[N_NODES + 1];           // CSR row offsets (by dst)
__device__ int    g_cursor[N_NODES];
__device__ float2 g_edge[N_EDGES];              // packed per CSR slot: {.x=src bits, .y=weight}
__device__ int    g_blocksums[NB];

// ---- 1. init counters ----
__global__ void k_init() {
    int i = blockIdx.x * blockDim.x + threadIdx.x;
    if (i < N_NODES) { g_cnt[i] = 0; g_nonisol[i] = 0; }
}

// ---- 2. count dst occurrences + mark non-isolated ----
__global__ void k_count(const int* __restrict__ src, const int* __restrict__ dst) {
    int e = blockIdx.x * blockDim.x + threadIdx.x;
    if (e < N_EDGES) {
        int s = src[e], d = dst[e];
        atomicAdd(&g_cnt[d], 1);
        g_nonisol[s] = 1;
        g_nonisol[d] = 1;
    }
}

// ---- 3. normalization coefficients ----
__global__ void k_norm() {
    int i = blockIdx.x * blockDim.x + threadIdx.x;
    if (i < N_NODES) {
        float deg = (float)(1 + g_cnt[i]);
        float inv = rsqrtf(deg);
        g_inv_sqrt[i] = inv;
        g_self[i] = inv * inv;
    }
}

// ---- 4. masked copy of input features into g_h[0] (float4 vectorized) ----
__global__ void k_mask(const float* __restrict__ x) {
    int j = blockIdx.x * blockDim.x + threadIdx.x;   // float4 index
    if (j < N_NODES * (D_FEAT / 4)) {
        int n = j / (D_FEAT / 4);
        float4 v = ((const float4*)x)[j];
        if (!g_nonisol[n]) { v.x = 0.f; v.y = 0.f; v.z = 0.f; v.w = 0.f; }
        ((float4*)g_h[0])[j] = v;
    }
}

// ---- 5a. per-block exclusive scan of g_cnt -> g_row, block totals -> g_blocksums ----
__global__ void k_scan_local() {
    __shared__ int s[SCAN_B];
    int tid = threadIdx.x;
    int i = blockIdx.x * SCAN_B + tid;
    int v = (i < N_NODES) ? g_cnt[i] : 0;
    s[tid] = v;
    __syncthreads();
    for (int off = 1; off < SCAN_B; off <<= 1) {
        int t = (tid >= off) ? s[tid - off] : 0;
        __syncthreads();
        s[tid] += t;
        __syncthreads();
    }
    if (i < N_NODES) g_row[i] = s[tid] - v;          // exclusive
    if (tid == SCAN_B - 1) g_blocksums[blockIdx.x] = s[tid];
}

// ---- 5b. scan block sums (tiny; single thread) ----
__global__ void k_scan_block() {
    if (threadIdx.x == 0) {
        int acc = 0;
        for (int b = 0; b < NB; b++) {
            int t = g_blocksums[b];
            g_blocksums[b] = acc;
            acc += t;
        }
    }
}

// ---- 5c. add block offsets, init cursors, cap row array ----
__global__ void k_scan_add() {
    int i = blockIdx.x * blockDim.x + threadIdx.x;
    if (i < N_NODES) {
        int r = g_row[i] + g_blocksums[i / SCAN_B];
        g_row[i] = r;
        g_cursor[i] = r;
    }
    if (i == 0) g_row[N_NODES] = N_EDGES;
}

// ---- 6. place edges into CSR slots, precompute edge weights (packed) ----
__global__ void k_place(const int* __restrict__ src, const int* __restrict__ dst) {
    int e = blockIdx.x * blockDim.x + threadIdx.x;
    if (e < N_EDGES) {
        int s = src[e], d = dst[e];
        int pos = atomicAdd(&g_cursor[d], 1);
        float2 rec;
        rec.x = __int_as_float(s);
        rec.y = g_inv_sqrt[s] * g_inv_sqrt[d];
        g_edge[pos] = rec;
    }
}

// ---- 7. one GCN propagation layer: warp per node ----
// lanes 0-15 handle features of even-indexed edges, 16-31 odd-indexed.
__global__ __launch_bounds__(256) void k_prop(int sel_in, float* __restrict__ dout) {
    int warp = (blockIdx.x * blockDim.x + threadIdx.x) >> 5;
    if (warp >= N_NODES) return;
    int lane = threadIdx.x & 31;
    int feat = lane & 15;
    int half = lane >> 4;

    const float* __restrict__ hin = g_h[sel_in];
    float* __restrict__ hout = dout ? dout : g_h[sel_in ^ 1];

    int beg = g_row[warp];
    int end = g_row[warp + 1];

    float acc = 0.f;
    for (int e = beg + half; e < end; e += 2) {
        float2 rec = g_edge[e];                 // single 8B load, uniform per half-warp
        int s = __float_as_int(rec.x);
        acc += rec.y * hin[s * D_FEAT + feat];
    }
    // fold odd-edge half into even half
    acc += __shfl_down_sync(0xffffffffu, acc, 16);
    if (half == 0) {
        hout[warp * D_FEAT + feat] = acc + g_self[warp] * hin[warp * D_FEAT + feat];
    }
}

extern "C" void kernel_launch(void* const* d_in, const int* in_sizes, int n_in,
                              void* d_out, int out_size) {
    const float* x  = (const float*)d_in[0];
    const int*   ei = (const int*)d_in[1];
    const int* src = ei;
    const int* dst = ei + N_EDGES;
    float* out = (float*)d_out;

    const int TB = 256;
    k_init <<<(N_NODES + TB - 1) / TB, TB>>>();
    k_count<<<(N_EDGES + TB - 1) / TB, TB>>>(src, dst);
    k_norm <<<(N_NODES + TB - 1) / TB, TB>>>();
    k_mask <<<(N_NODES * (D_FEAT / 4) + TB - 1) / TB, TB>>>(x);
    k_scan_local<<<NB, SCAN_B>>>();
    k_scan_block<<<1, 32>>>();
    k_scan_add<<<(N_NODES + TB - 1) / TB, TB>>>();
    k_place<<<(N_EDGES + TB - 1) / TB, TB>>>(src, dst);

    int total_threads = N_NODES * 32;
    int blocks = (total_threads + TB - 1) / TB;
    for (int l = 0; l < N_LAYERS; l++) {
        k_prop<<<blocks, TB>>>(l & 1, (l == N_LAYERS - 1) ? out : nullptr);
    }
}

// round 5
// speedup vs baseline: 1.1063x; 1.1063x over previous
#include <cuda_runtime.h>
#include <cuda_bf16.h>

// Problem constants (match reference_code)
#define N_NODES 100000
#define N_EDGES 3200000
#define D_FEAT  16
#define N_LAYERS 12

#define SCAN_B 1024
#define NB ((N_NODES + SCAN_B - 1) / SCAN_B)

// ---- scratch (device globals; no allocation allowed) ----
__device__ float  g_h[2][N_NODES * D_FEAT];     // ping-pong feature buffers
__device__ float  g_inv_sqrt[N_NODES];
__device__ float  g_self[N_NODES];              // 1/deg
__device__ int    g_cnt[N_NODES];               // dst-degree counts
__device__ int    g_nonisol[N_NODES];
__device__ int    g_row[N_NODES + 1];           // CSR row offsets (by dst)
__device__ int    g_cursor[N_NODES];
__device__ float2 g_edge[N_EDGES];              // packed per CSR slot: {.x=src bits, .y=weight}
__device__ int    g_blocksums[NB];

// ---- 1. init counters ----
__global__ void k_init() {
    int i = blockIdx.x * blockDim.x + threadIdx.x;
    if (i < N_NODES) { g_cnt[i] = 0; g_nonisol[i] = 0; }
}

// ---- 2. count dst occurrences + mark non-isolated ----
__global__ void k_count(const int* __restrict__ src, const int* __restrict__ dst) {
    int e = blockIdx.x * blockDim.x + threadIdx.x;
    if (e < N_EDGES) {
        int s = src[e], d = dst[e];
        atomicAdd(&g_cnt[d], 1);
        g_nonisol[s] = 1;
        g_nonisol[d] = 1;
    }
}

// ---- 3. normalization coefficients ----
__global__ void k_norm() {
    int i = blockIdx.x * blockDim.x + threadIdx.x;
    if (i < N_NODES) {
        float deg = (float)(1 + g_cnt[i]);
        float inv = rsqrtf(deg);
        g_inv_sqrt[i] = inv;
        g_self[i] = inv * inv;
    }
}

// ---- 4. masked copy of input features into g_h[0] (float4 vectorized) ----
__global__ void k_mask(const float* __restrict__ x) {
    int j = blockIdx.x * blockDim.x + threadIdx.x;   // float4 index
    if (j < N_NODES * (D_FEAT / 4)) {
        int n = j / (D_FEAT / 4);
        float4 v = ((const float4*)x)[j];
        if (!g_nonisol[n]) { v.x = 0.f; v.y = 0.f; v.z = 0.f; v.w = 0.f; }
        ((float4*)g_h[0])[j] = v;
    }
}

// ---- 5a. per-block exclusive scan of g_cnt -> g_row, block totals -> g_blocksums ----
__global__ void k_scan_local() {
    __shared__ int s[SCAN_B];
    int tid = threadIdx.x;
    int i = blockIdx.x * SCAN_B + tid;
    int v = (i < N_NODES) ? g_cnt[i] : 0;
    s[tid] = v;
    __syncthreads();
    for (int off = 1; off < SCAN_B; off <<= 1) {
        int t = (tid >= off) ? s[tid - off] : 0;
        __syncthreads();
        s[tid] += t;
        __syncthreads();
    }
    if (i < N_NODES) g_row[i] = s[tid] - v;          // exclusive
    if (tid == SCAN_B - 1) g_blocksums[blockIdx.x] = s[tid];
}

// ---- 5b. scan block sums (tiny; single thread) ----
__global__ void k_scan_block() {
    if (threadIdx.x == 0) {
        int acc = 0;
        for (int b = 0; b < NB; b++) {
            int t = g_blocksums[b];
            g_blocksums[b] = acc;
            acc += t;
        }
    }
}

// ---- 5c. add block offsets, init cursors, cap row array ----
__global__ void k_scan_add() {
    int i = blockIdx.x * blockDim.x + threadIdx.x;
    if (i < N_NODES) {
        int r = g_row[i] + g_blocksums[i / SCAN_B];
        g_row[i] = r;
        g_cursor[i] = r;
    }
    if (i == 0) g_row[N_NODES] = N_EDGES;
}

// ---- 6. place edges into CSR slots, precompute edge weights (packed) ----
__global__ void k_place(const int* __restrict__ src, const int* __restrict__ dst) {
    int e = blockIdx.x * blockDim.x + threadIdx.x;
    if (e < N_EDGES) {
        int s = src[e], d = dst[e];
        int pos = atomicAdd(&g_cursor[d], 1);
        float2 rec;
        rec.x = __int_as_float(s);
        rec.y = g_inv_sqrt[s] * g_inv_sqrt[d];
        g_edge[pos] = rec;
    }
}

// ---- 7. one GCN propagation layer: warp per node, 4 lanes per edge ----
// lane>>2 = edge group (8 edges in flight), lane&3 = float4 feature slot.
__global__ __launch_bounds__(256) void k_prop(int sel_in, float* __restrict__ dout) {
    int warp = (blockIdx.x * blockDim.x + threadIdx.x) >> 5;
    if (warp >= N_NODES) return;
    int lane = threadIdx.x & 31;
    int grp  = lane >> 2;    // 0..7: which edge in the 8-wide batch
    int f4   = lane & 3;     // 0..3: which float4 of the 16-float row

    const float* __restrict__ hin = g_h[sel_in];
    float* __restrict__ hout = dout ? dout : g_h[sel_in ^ 1];

    int beg = g_row[warp];
    int end = g_row[warp + 1];

    float4 acc = make_float4(0.f, 0.f, 0.f, 0.f);
    #pragma unroll 2
    for (int e = beg + grp; e < end; e += 8) {
        float2 rec = g_edge[e];                 // 8B, broadcast within 4-lane group
        int s = __float_as_int(rec.x);
        float4 v = ((const float4*)(hin + s * D_FEAT))[f4];   // LDG.128, 8 rows/warp
        acc.x += rec.y * v.x;
        acc.y += rec.y * v.y;
        acc.z += rec.y * v.z;
        acc.w += rec.y * v.w;
    }

    // reduce the 8 edge-groups (lane bits [4:2]) into every lane
    #pragma unroll
    for (int off = 16; off >= 4; off >>= 1) {
        acc.x += __shfl_xor_sync(0xffffffffu, acc.x, off);
        acc.y += __shfl_xor_sync(0xffffffffu, acc.y, off);
        acc.z += __shfl_xor_sync(0xffffffffu, acc.z, off);
        acc.w += __shfl_xor_sync(0xffffffffu, acc.w, off);
    }

    if (lane < 4) {
        float sc = g_self[warp];
        float4 hv = ((const float4*)(hin + warp * D_FEAT))[lane];
        float4 o;
        o.x = acc.x + sc * hv.x;
        o.y = acc.y + sc * hv.y;
        o.z = acc.z + sc * hv.z;
        o.w = acc.w + sc * hv.w;
        ((float4*)(hout + warp * D_FEAT))[lane] = o;
    }
}

extern "C" void kernel_launch(void* const* d_in, const int* in_sizes, int n_in,
                              void* d_out, int out_size) {
    const float* x  = (const float*)d_in[0];
    const int*   ei = (const int*)d_in[1];
    const int* src = ei;
    const int* dst = ei + N_EDGES;
    float* out = (float*)d_out;

    const int TB = 256;
    k_init <<<(N_NODES + TB - 1) / TB, TB>>>();
    k_count<<<(N_EDGES + TB - 1) / TB, TB>>>(src, dst);
    k_norm <<<(N_NODES + TB - 1) / TB, TB>>>();
    k_mask <<<(N_NODES * (D_FEAT / 4) + TB - 1) / TB, TB>>>(x);
    k_scan_local<<<NB, SCAN_B>>>();
    k_scan_block<<<1, 32>>>();
    k_scan_add<<<(N_NODES + TB - 1) / TB, TB>>>();
    k_place<<<(N_EDGES + TB - 1) / TB, TB>>>(src, dst);

    int total_threads = N_NODES * 32;
    int blocks = (total_threads + TB - 1) / TB;
    for (int l = 0; l < N_LAYERS; l++) {
        k_prop<<<blocks, TB>>>(l & 1, (l == N_LAYERS - 1) ? out : nullptr);
    }
}

// round 8
// speedup vs baseline: 1.1971x; 1.0821x over previous
#include <cuda_runtime.h>
#include <cuda_bf16.h>

// Problem constants (match reference_code)
#define N_NODES 100000
#define N_EDGES 3200000
#define D_FEAT  16
#define N_LAYERS 12

#define SCAN_B 1024
#define NB ((N_NODES + SCAN_B - 1) / SCAN_B)

// ---- scratch (device globals; no allocation allowed) ----
__device__ float  g_h[2][N_NODES * D_FEAT];     // ping-pong scaled-feature buffers (hhat = inv_sqrt * h)
__device__ float  g_inv_sqrt[N_NODES];
__device__ float  g_self[N_NODES];              // inv_sqrt^2 = 1/deg
__device__ int    g_cnt[N_NODES];               // dst-degree counts
__device__ int    g_nonisol[N_NODES];
__device__ int    g_row[N_NODES + 1];           // CSR row offsets (by dst)
__device__ int    g_cursor[N_NODES];
__device__ int    g_src[N_EDGES];               // src index per CSR slot (weight eliminated)
__device__ int    g_blocksums[NB];

// ---- 1. init counters ----
__global__ void k_init() {
    int i = blockIdx.x * blockDim.x + threadIdx.x;
    if (i < N_NODES) { g_cnt[i] = 0; g_nonisol[i] = 0; }
}

// ---- 2. count dst occurrences + mark non-isolated ----
__global__ void k_count(const int* __restrict__ src, const int* __restrict__ dst) {
    int e = blockIdx.x * blockDim.x + threadIdx.x;
    if (e < N_EDGES) {
        int s = src[e], d = dst[e];
        atomicAdd(&g_cnt[d], 1);
        g_nonisol[s] = 1;
        g_nonisol[d] = 1;
    }
}

// ---- 3. normalization coefficients ----
__global__ void k_norm() {
    int i = blockIdx.x * blockDim.x + threadIdx.x;
    if (i < N_NODES) {
        float deg = (float)(1 + g_cnt[i]);
        float inv = rsqrtf(deg);
        g_inv_sqrt[i] = inv;
        g_self[i] = inv * inv;
    }
}

// ---- 4. masked + pre-scaled copy: hhat0 = inv_sqrt * (masked x) ----
__global__ void k_mask(const float* __restrict__ x) {
    int j = blockIdx.x * blockDim.x + threadIdx.x;   // float4 index
    if (j < N_NODES * (D_FEAT / 4)) {
        int n = j / (D_FEAT / 4);
        float4 v = ((const float4*)x)[j];
        float sc = g_nonisol[n] ? g_inv_sqrt[n] : 0.f;
        v.x *= sc; v.y *= sc; v.z *= sc; v.w *= sc;
        ((float4*)g_h[0])[j] = v;
    }
}

// ---- 5a. per-block exclusive scan of g_cnt -> g_row, block totals -> g_blocksums ----
__global__ void k_scan_local() {
    __shared__ int s[SCAN_B];
    int tid = threadIdx.x;
    int i = blockIdx.x * SCAN_B + tid;
    int v = (i < N_NODES) ? g_cnt[i] : 0;
    s[tid] = v;
    __syncthreads();
    for (int off = 1; off < SCAN_B; off <<= 1) {
        int t = (tid >= off) ? s[tid - off] : 0;
        __syncthreads();
        s[tid] += t;
        __syncthreads();
    }
    if (i < N_NODES) g_row[i] = s[tid] - v;          // exclusive
    if (tid == SCAN_B - 1) g_blocksums[blockIdx.x] = s[tid];
}

// ---- 5b. scan block sums (tiny; single thread) ----
__global__ void k_scan_block() {
    if (threadIdx.x == 0) {
        int acc = 0;
        for (int b = 0; b < NB; b++) {
            int t = g_blocksums[b];
            g_blocksums[b] = acc;
            acc += t;
        }
    }
}

// ---- 5c. add block offsets, init cursors, cap row array ----
__global__ void k_scan_add() {
    int i = blockIdx.x * blockDim.x + threadIdx.x;
    if (i < N_NODES) {
        int r = g_row[i] + g_blocksums[i / SCAN_B];
        g_row[i] = r;
        g_cursor[i] = r;
    }
    if (i == 0) g_row[N_NODES] = N_EDGES;
}

// ---- 6. place edges into CSR slots (src only; no weights needed) ----
__global__ void k_place(const int* __restrict__ src, const int* __restrict__ dst) {
    int e = blockIdx.x * blockDim.x + threadIdx.x;
    if (e < N_EDGES) {
        int s = src[e], d = dst[e];
        int pos = atomicAdd(&g_cursor[d], 1);
        g_src[pos] = s;
    }
}

// ---- 7. one scaled-GCN layer: warp per node, 4 lanes per edge ----
// hhat_new[d] = fac[d] * (sum_{e->d} hhat[src] + hhat[d])
// fac = g_self for inner layers, g_inv_sqrt for the final layer (un-scales output).
__global__ __launch_bounds__(256) void k_prop(int sel_in, float* __restrict__ dout, int last) {
    int warp = (blockIdx.x * blockDim.x + threadIdx.x) >> 5;
    if (warp >= N_NODES) return;
    int lane = threadIdx.x & 31;
    int grp  = lane >> 2;    // 0..7: which edge in the 8-wide batch
    int f4   = lane & 3;     // 0..3: which float4 of the 16-float row

    const float* __restrict__ hin = g_h[sel_in];
    float* __restrict__ hout = dout ? dout : g_h[sel_in ^ 1];
    const float* __restrict__ fac = last ? g_inv_sqrt : g_self;

    int beg = g_row[warp];
    int end = g_row[warp + 1];

    float4 acc = make_float4(0.f, 0.f, 0.f, 0.f);
    #pragma unroll 2
    for (int e = beg + grp; e < end; e += 8) {
        int s = __ldg(&g_src[e]);               // 4B, broadcast within 4-lane group
        float4 v = ((const float4*)(hin + s * D_FEAT))[f4];   // LDG.128, 8 rows/warp
        acc.x += v.x;
        acc.y += v.y;
        acc.z += v.z;
        acc.w += v.w;
    }

    // reduce the 8 edge-groups (lane bits [4:2]) into every lane
    #pragma unroll
    for (int off = 16; off >= 4; off >>= 1) {
        acc.x += __shfl_xor_sync(0xffffffffu, acc.x, off);
        acc.y += __shfl_xor_sync(0xffffffffu, acc.y, off);
        acc.z += __shfl_xor_sync(0xffffffffu, acc.z, off);
        acc.w += __shfl_xor_sync(0xffffffffu, acc.w, off);
    }

    if (lane < 4) {
        float sc = fac[warp];
        float4 hv = ((const float4*)(hin + warp * D_FEAT))[lane];
        float4 o;
        o.x = sc * (acc.x + hv.x);
        o.y = sc * (acc.y + hv.y);
        o.z = sc * (acc.z + hv.z);
        o.w = sc * (acc.w + hv.w);
        ((float4*)(hout + warp * D_FEAT))[lane] = o;
    }
}

extern "C" void kernel_launch(void* const* d_in, const int* in_sizes, int n_in,
                              void* d_out, int out_size) {
    const float* x  = (const float*)d_in[0];
    const int*   ei = (const int*)d_in[1];
    const int* src = ei;
    const int* dst = ei + N_EDGES;
    float* out = (float*)d_out;

    const int TB = 256;
    k_init <<<(N_NODES + TB - 1) / TB, TB>>>();
    k_count<<<(N_EDGES + TB - 1) / TB, TB>>>(src, dst);
    k_norm <<<(N_NODES + TB - 1) / TB, TB>>>();
    k_mask <<<(N_NODES * (D_FEAT / 4) + TB - 1) / TB, TB>>>(x);
    k_scan_local<<<NB, SCAN_B>>>();
    k_scan_block<<<1, 32>>>();
    k_scan_add<<<(N_NODES + TB - 1) / TB, TB>>>();
    k_place<<<(N_EDGES + TB - 1) / TB, TB>>>(src, dst);

    int total_threads = N_NODES * 32;
    int blocks = (total_threads + TB - 1) / TB;
    for (int l = 0; l < N_LAYERS; l++) {
        int last = (l == N_LAYERS - 1);
        k_prop<<<blocks, TB>>>(l & 1, last ? out : nullptr, last);
    }
}

// round 11
// speedup vs baseline: 1.2946x; 1.0815x over previous
#include <cuda_runtime.h>
#include <cuda_bf16.h>

// Problem constants (match reference_code)
#define N_NODES 100000
#define N_EDGES 3200000
#define D_FEAT  16
#define N_LAYERS 12

#define SCAN_B 1024
#define NB ((N_NODES + SCAN_B - 1) / SCAN_B)

// ---- scratch (device globals; no allocation allowed) ----
__device__ float  g_h[2][N_NODES * D_FEAT];     // ping-pong scaled-feature buffers (hhat = inv_sqrt * h)
__device__ float  g_inv_sqrt[N_NODES];
__device__ float  g_self[N_NODES];              // inv_sqrt^2 = 1/deg
__device__ int    g_cnt[N_NODES];               // dst-degree counts
__device__ int    g_nonisol[N_NODES];           // set only from src side; dst side implied by cnt>0
__device__ int    g_row[N_NODES + 1];           // CSR row offsets (by dst)
__device__ int    g_cursor[N_NODES];
__device__ int    g_src[N_EDGES];               // src index per CSR slot (weight eliminated)
__device__ int    g_blocksums[NB];

// ---- 1. init counters ----
__global__ void k_init() {
    int i = blockIdx.x * blockDim.x + threadIdx.x;
    if (i < N_NODES) { g_cnt[i] = 0; g_nonisol[i] = 0; }
}

// ---- 2. count dst occurrences + mark src non-isolation (2 edges/thread) ----
__global__ void k_count(const int* __restrict__ src, const int* __restrict__ dst) {
    int t = blockIdx.x * blockDim.x + threadIdx.x;
    if (t < N_EDGES / 2) {
        int2 s2 = ((const int2*)src)[t];
        int2 d2 = ((const int2*)dst)[t];
        atomicAdd(&g_cnt[d2.x], 1);
        atomicAdd(&g_cnt[d2.y], 1);
        g_nonisol[s2.x] = 1;
        g_nonisol[s2.y] = 1;
    }
}

// ---- 3a. per-block exclusive scan of g_cnt -> g_row (+ fused norm coefficients) ----
__global__ void k_scan_local() {
    __shared__ int s[SCAN_B];
    int tid = threadIdx.x;
    int i = blockIdx.x * SCAN_B + tid;
    int v = (i < N_NODES) ? g_cnt[i] : 0;
    if (i < N_NODES) {
        float inv = rsqrtf((float)(1 + v));
        g_inv_sqrt[i] = inv;
        g_self[i] = inv * inv;
    }
    s[tid] = v;
    __syncthreads();
    for (int off = 1; off < SCAN_B; off <<= 1) {
        int t = (tid >= off) ? s[tid - off] : 0;
        __syncthreads();
        s[tid] += t;
        __syncthreads();
    }
    if (i < N_NODES) g_row[i] = s[tid] - v;          // exclusive
    if (tid == SCAN_B - 1) g_blocksums[blockIdx.x] = s[tid];
}

// ---- 3b. scan block sums (tiny; single thread) ----
__global__ void k_scan_block() {
    if (threadIdx.x == 0) {
        int acc = 0;
        for (int b = 0; b < NB; b++) {
            int t = g_blocksums[b];
            g_blocksums[b] = acc;
            acc += t;
        }
    }
}

// ---- 3c. add block offsets, init cursors, cap row array ----
__global__ void k_scan_add() {
    int i = blockIdx.x * blockDim.x + threadIdx.x;
    if (i < N_NODES) {
        int r = g_row[i] + g_blocksums[i / SCAN_B];
        g_row[i] = r;
        g_cursor[i] = r;
    }
    if (i == 0) g_row[N_NODES] = N_EDGES;
}

// ---- 4. masked + pre-scaled copy: hhat0 = inv_sqrt * (masked x) ----
// non-isolated  <=>  appeared as src (g_nonisol) OR as dst (g_cnt > 0)
__global__ void k_mask(const float* __restrict__ x) {
    int j = blockIdx.x * blockDim.x + threadIdx.x;   // float4 index
    if (j < N_NODES * (D_FEAT / 4)) {
        int n = j / (D_FEAT / 4);
        float4 v = ((const float4*)x)[j];
        float sc = (g_nonisol[n] || g_cnt[n]) ? g_inv_sqrt[n] : 0.f;
        v.x *= sc; v.y *= sc; v.z *= sc; v.w *= sc;
        ((float4*)g_h[0])[j] = v;
    }
}

// ---- 5. place edges into CSR slots (src only; 2 edges/thread) ----
__global__ void k_place(const int* __restrict__ src, const int* __restrict__ dst) {
    int t = blockIdx.x * blockDim.x + threadIdx.x;
    if (t < N_EDGES / 2) {
        int2 s2 = ((const int2*)src)[t];
        int2 d2 = ((const int2*)dst)[t];
        int p0 = atomicAdd(&g_cursor[d2.x], 1);
        g_src[p0] = s2.x;
        int p1 = atomicAdd(&g_cursor[d2.y], 1);
        g_src[p1] = s2.y;
    }
}

// ---- 6. one scaled-GCN layer: warp per node, 4 lanes per edge ----
// hhat_new[d] = fac[d] * (sum_{e->d} hhat[src] + hhat[d])
// fac = g_self for inner layers, g_inv_sqrt for the final layer (un-scales output).
__global__ __launch_bounds__(256) void k_prop(int sel_in, float* __restrict__ dout, int last) {
    int warp = (blockIdx.x * blockDim.x + threadIdx.x) >> 5;
    if (warp >= N_NODES) return;
    int lane = threadIdx.x & 31;
    int grp  = lane >> 2;    // 0..7: which edge in the 8-wide batch
    int f4   = lane & 3;     // 0..3: which float4 of the 16-float row

    const float* __restrict__ hin = g_h[sel_in];
    float* __restrict__ hout = dout ? dout : g_h[sel_in ^ 1];
    const float* __restrict__ fac = last ? g_inv_sqrt : g_self;

    int beg = g_row[warp];
    int end = g_row[warp + 1];

    float4 acc = make_float4(0.f, 0.f, 0.f, 0.f);
    #pragma unroll 2
    for (int e = beg + grp; e < end; e += 8) {
        int s = __ldg(&g_src[e]);               // 4B, broadcast within 4-lane group
        float4 v = ((const float4*)(hin + s * D_FEAT))[f4];   // LDG.128, 8 rows/warp
        acc.x += v.x;
        acc.y += v.y;
        acc.z += v.z;
        acc.w += v.w;
    }

    // reduce the 8 edge-groups (lane bits [4:2]) into every lane
    #pragma unroll
    for (int off = 16; off >= 4; off >>= 1) {
        acc.x += __shfl_xor_sync(0xffffffffu, acc.x, off);
        acc.y += __shfl_xor_sync(0xffffffffu, acc.y, off);
        acc.z += __shfl_xor_sync(0xffffffffu, acc.z, off);
        acc.w += __shfl_xor_sync(0xffffffffu, acc.w, off);
    }

    if (lane < 4) {
        float sc = fac[warp];
        float4 hv = ((const float4*)(hin + warp * D_FEAT))[lane];
        float4 o;
        o.x = sc * (acc.x + hv.x);
        o.y = sc * (acc.y + hv.y);
        o.z = sc * (acc.z + hv.z);
        o.w = sc * (acc.w + hv.w);
        ((float4*)(hout + warp * D_FEAT))[lane] = o;
    }
}

extern "C" void kernel_launch(void* const* d_in, const int* in_sizes, int n_in,
                              void* d_out, int out_size) {
    const float* x  = (const float*)d_in[0];
    const int*   ei = (const int*)d_in[1];
    const int* src = ei;
    const int* dst = ei + N_EDGES;
    float* out = (float*)d_out;

    const int TB = 256;
    k_init <<<(N_NODES + TB - 1) / TB, TB>>>();
    k_count<<<(N_EDGES / 2 + TB - 1) / TB, TB>>>(src, dst);
    k_scan_local<<<NB, SCAN_B>>>();
    k_scan_block<<<1, 32>>>();
    k_scan_add<<<(N_NODES + TB - 1) / TB, TB>>>();
    k_mask <<<(N_NODES * (D_FEAT / 4) + TB - 1) / TB, TB>>>(x);
    k_place<<<(N_EDGES / 2 + TB - 1) / TB, TB>>>(src, dst);

    int total_threads = N_NODES * 32;
    int blocks = (total_threads + TB - 1) / TB;
    for (int l = 0; l < N_LAYERS; l++) {
        int last = (l == N_LAYERS - 1);
        k_prop<<<blocks, TB>>>(l & 1, last ? out : nullptr, last);
    }
}